// round 16
// baseline (speedup 1.0000x reference)
#include <cuda_runtime.h>
#include <cuda_fp16.h>
#include <math.h>
#include <cstdint>

#define NB 4
#define NL 1024
#define ND 1024
#define NH 16
#define NHD 64
#define NBH (NB*NH)

// ---------------- scratch (device globals) ----------------
__device__ __align__(16) __half g_qcat[NBH*NL*192];     // [bh][l][pq|hq|vq]
__device__ __align__(16) __half g_kcat[NBH*NL*192];     // [bh][l][k|cf|bf]
__device__ __align__(16) __half g_vt[NBH*NHD*NL];       // [bh][hd][l]
__device__ __align__(16) __half g_ctx[NB*NL*ND];
__device__ __align__(16) __half g_pp[(size_t)NBH*NL*NL]; // fp16 exp(s - m_tile)
__device__ __align__(16) __half g_wt[6u*1024u*1024u];
__device__ __align__(16) __half g_qh[NB*NL*ND];
__device__ __align__(16) __half g_kh[NB*NL*ND];
__device__ __align__(16) __half g_vh[NB*NL*ND];
__device__ __align__(16) float  g_bcat[3072];
__device__ __align__(16) float  g_pmax[NBH*NL*8];
__device__ __align__(16) float  g_psum[NBH*NL*8];

// ---------------- helpers ----------------
__device__ __forceinline__ void cpa16(uint32_t s, const void* g) {
    asm volatile("cp.async.cg.shared.global [%0], [%1], 16;" :: "r"(s), "l"(g) : "memory");
}
__device__ __forceinline__ uint32_t s2u(const void* p) {
    return (uint32_t)__cvta_generic_to_shared(p);
}
__device__ __forceinline__ void ldsm4(uint32_t (&r)[4], uint32_t a) {
    asm volatile("ldmatrix.sync.aligned.m8n8.x4.shared.b16 {%0,%1,%2,%3}, [%4];"
        : "=r"(r[0]), "=r"(r[1]), "=r"(r[2]), "=r"(r[3]) : "r"(a));
}
__device__ __forceinline__ void mma16816(float (&d)[4], const uint32_t (&a)[4], uint32_t b0, uint32_t b1) {
    asm volatile(
        "mma.sync.aligned.m16n8k16.row.col.f32.f16.f16.f32 "
        "{%0,%1,%2,%3}, {%4,%5,%6,%7}, {%8,%9}, {%0,%1,%2,%3};"
        : "+f"(d[0]), "+f"(d[1]), "+f"(d[2]), "+f"(d[3])
        : "r"(a[0]), "r"(a[1]), "r"(a[2]), "r"(a[3]), "r"(b0), "r"(b1));
}

#define BP_BIG 144    // byte pitch, rows of 64 fp16
#define BP_CTX 80     // byte pitch, rows of 32 fp16
#define NSTG 3

template<int MSUB, int NB16, int KSTEPS, int AP, int BPP>
__device__ __forceinline__ void warp_mma_h(
    uint32_t aBase, uint32_t bBase, float (&acc)[MSUB][NB16*2][4])
{
#pragma unroll
    for (int ks = 0; ks < KSTEPS; ks++) {
        uint32_t a[MSUB][4];
#pragma unroll
        for (int mi = 0; mi < MSUB; mi++)
            ldsm4(a[mi], aBase + mi*16*AP + ks*32);
        uint32_t b[NB16*2][2];
#pragma unroll
        for (int nj = 0; nj < NB16; nj++) {
            uint32_t r[4];
            ldsm4(r, bBase + nj*16*BPP + ks*32);
            b[2*nj+0][0] = r[0]; b[2*nj+0][1] = r[2];
            b[2*nj+1][0] = r[1]; b[2*nj+1][1] = r[3];
        }
#pragma unroll
        for (int mi = 0; mi < MSUB; mi++)
#pragma unroll
            for (int ni = 0; ni < NB16*2; ni++)
                mma16816(acc[mi][ni], a[mi], b[ni][0], b[ni][1]);
    }
}

#define LAY_QCAT 0
#define LAY_KCAT 1
#define LAY_VT   2

#define FRAG_COORDS()                                                   \
    const int lane = tid & 31, wid = tid >> 5;                          \
    const int wm = wid & 1, wn = wid >> 1;                              \
    const int g = lane >> 2, t = lane & 3;                              \
    const int rF = (lane & 7) + ((lane >> 3) & 1)*8;                    \
    const int cF = (lane >> 4) * 16

// ============================================================
// prologue: ONE launch = convert3 | transpose6 | chordfeat | concat
// ============================================================
struct ProArgs {
    const float4 *q, *k, *v;
    __half2 *qh, *kh, *vh;
    const float* wsrc[6];
    __half* wdst[6];
    const int *pc, *bon;
    const float *Wc, *bcW, *Wb, *bbW;
    __half* kcat;
    const float *bpq, *bhq, *bvq;
    float* bcat;
};

__global__ void __launch_bounds__(256) prologue(ProArgs p)
{
    __shared__ float tbuf[32][33];
    const int bid = blockIdx.x, tid = threadIdx.x;

    if (bid < 12288) {
        int i = bid*256 + tid;
        int seg = i >> 20, j = i & 1048575;
        const float4* in = (seg == 0) ? p.q : (seg == 1) ? p.k : p.v;
        __half2* out = (seg == 0) ? p.qh : (seg == 1) ? p.kh : p.vh;
        float4 x = in[j];
        out[j*2]   = __floats2half2_rn(x.x, x.y);
        out[j*2+1] = __floats2half2_rn(x.z, x.w);
    } else if (bid < 18432) {
        int w = bid - 12288;
        int z = w >> 10, tile = w & 1023;
        const float* src = p.wsrc[z];
        __half* dst = p.wdst[z];
        int bx = (tile & 31) * 32, by = (tile >> 5) * 32;
        int x = tid & 31, y0 = tid >> 5;
#pragma unroll
        for (int dy = 0; dy < 32; dy += 8)
            tbuf[y0+dy][x] = src[(size_t)(by + y0 + dy)*1024 + bx + x];
        __syncthreads();
#pragma unroll
        for (int dy = 0; dy < 32; dy += 8)
            dst[(size_t)(bx + y0 + dy)*1024 + by + x] = __float2half_rn(tbuf[x][y0+dy]);
    } else if (bid < 22528) {
        int idx = (bid - 18432)*256 + tid;
        int l = idx >> 10, n = idx & 1023;
        float sc = p.bcW[n], sb = p.bbW[n];
#pragma unroll
        for (int q = 0; q < 12; q++) {
            sc += (float)p.pc[l*12 + q] * p.Wc[q*1024 + n];
            sb += (float)p.bon[l*12 + q] * p.Wb[q*1024 + n];
        }
        __half hc = __float2half_rn(sc), hb = __float2half_rn(sb);
        int h = n >> 6, hd = n & 63;
#pragma unroll
        for (int b = 0; b < 4; b++) {
            size_t row = ((size_t)((b*16 + h)*1024 + l))*192;
            p.kcat[row + 64 + hd]  = hc;
            p.kcat[row + 128 + hd] = hb;
        }
    } else {
        int i = (bid - 22528)*256 + tid;
        p.bcat[i] = (i < 1024) ? p.bpq[i] : (i < 2048) ? p.bhq[i - 1024] : p.bvq[i - 2048];
    }
}

// ============================================================
// mma_proj: 3 projection GEMMs; 256 thr, warp tile 64x32, BK=64
// ============================================================
struct ProjArgs {
    const __half* Aq; const __half* Ak; const __half* Av;
    const __half* Wq; const __half* Wk; const __half* Wv;
    const float* bq; const float* bk; const float* bv;
    __half* Cq; __half* Ck; __half* Cv;
};

__global__ void __launch_bounds__(256, 2) mma_proj(ProjArgs p)
{
    extern __shared__ char smc[];
    const int tid = threadIdx.x;
    FRAG_COORDS();
    uint32_t smu = s2u(smc);
    const int nb = blockIdx.x, m0 = blockIdx.y * 128;

    const __half *A, *BT; const float* bias; __half* C; int n0, lay;
    if (nb < 24)      { A = p.Aq; BT = p.Wq; bias = p.bq; C = p.Cq; n0 = nb*128;      lay = LAY_QCAT; }
    else if (nb < 32) { A = p.Ak; BT = p.Wk; bias = p.bk; C = p.Ck; n0 = (nb-24)*128; lay = LAY_KCAT; }
    else              { A = p.Av; BT = p.Wv; bias = p.bv; C = p.Cv; n0 = (nb-32)*128; lay = LAY_VT; }

    float acc[4][4][4] = {};
    const int lr_ = tid >> 3, lc_ = tid & 7;

#define LOAD_STAGE(i) do {                                                 \
        if ((i) < 16) {                                                    \
            int k0 = (i) * 64; uint32_t sb = smu + ((i) % NSTG)*2*128*BP_BIG; \
            _Pragma("unroll")                                              \
            for (int it = 0; it < 4; it++) {                               \
                int r = lr_ + it*32;                                       \
                cpa16(sb + r*BP_BIG + lc_*16, A  + (size_t)(m0+r)*1024 + k0 + lc_*8); \
                cpa16(sb + 128*BP_BIG + r*BP_BIG + lc_*16, BT + (size_t)(n0+r)*1024 + k0 + lc_*8); \
            }                                                              \
        }                                                                  \
        asm volatile("cp.async.commit_group;" ::: "memory");               \
    } while (0)

    LOAD_STAGE(0);
    LOAD_STAGE(1);
    for (int i = 0; i < 16; i++) {
        uint32_t sb = smu + (i % NSTG)*2*128*BP_BIG;
        asm volatile("cp.async.wait_group 1;" ::: "memory");
        __syncthreads();
        LOAD_STAGE(i + 2);
        warp_mma_h<4,2,4,BP_BIG,BP_BIG>(sb + (wm*64 + rF)*BP_BIG + cF,
                                        sb + 128*BP_BIG + (wn*32 + rF)*BP_BIG + cF, acc);
    }
#undef LOAD_STAGE

#pragma unroll
    for (int mi = 0; mi < 4; mi++)
#pragma unroll
        for (int ni = 0; ni < 4; ni++) {
            int mrow = m0 + wm*64 + mi*16 + g;
            int ncol = n0 + wn*32 + ni*8 + t*2;
            float b0 = bias[ncol], b1 = bias[ncol+1];
            float v00 = acc[mi][ni][0] + b0, v01 = acc[mi][ni][1] + b1;
            float v10 = acc[mi][ni][2] + b0, v11 = acc[mi][ni][3] + b1;
            int b = mrow >> 10, l = mrow & 1023;
            if (lay == LAY_VT) {
                int h = ncol >> 6, hd = ncol & 63;
                size_t base = ((size_t)((b*16 + h)*64 + hd)) * NL;
                C[base + l]          = __float2half_rn(v00);
                C[base + l + 8]      = __float2half_rn(v10);
                C[base + NL + l]     = __float2half_rn(v01);
                C[base + NL + l + 8] = __float2half_rn(v11);
            } else {
                int seg, nn;
                if (lay == LAY_QCAT) { seg = ncol >> 10; nn = ncol & 1023; }
                else                 { seg = 0;          nn = ncol; }
                int h = nn >> 6, hd = nn & 63;
                size_t r0 = ((size_t)((b*16 + h)*1024 + l))*192 + seg*64 + hd;
                size_t r1 = ((size_t)((b*16 + h)*1024 + l + 8))*192 + seg*64 + hd;
                *(__half2*)(C + r0) = __floats2half2_rn(v00, v01);
                *(__half2*)(C + r1) = __floats2half2_rn(v10, v11);
            }
        }
}

// ============================================================
// mma_out_fused: bid<256 -> output GEMM; bid>=256 -> attn fp32 writer
// writer: attn[row][col] = float(pp) * alpha[row][col>>7], streaming
// ============================================================
__global__ void __launch_bounds__(256, 2) mma_out_fused(
    const __half* __restrict__ A, const __half* __restrict__ BT,
    const float* __restrict__ bias, float* __restrict__ C,
    const __half* __restrict__ pp, const float* __restrict__ pmax,
    const float* __restrict__ psum, float* __restrict__ attn)
{
    extern __shared__ char smc[];
    const int tid = threadIdx.x;
    const int bid = blockIdx.x;

    if (bid >= 256) {
        // ---- attn writer block: (bh, q-tile) ----
        float* alpha = (float*)smc;                 // [128][8]
        const int w = bid - 256;
        const int bh = w >> 3, q0 = (w & 7) * 128;
        if (tid < 128) {
            size_t row = (size_t)bh*NL + q0 + tid;
            float m[8], s[8];
#pragma unroll
            for (int q = 0; q < 8; q++) { m[q] = pmax[row*8+q]; s[q] = psum[row*8+q]; }
            float M = m[0];
#pragma unroll
            for (int q = 1; q < 8; q++) M = fmaxf(M, m[q]);
            float S = 0.f;
#pragma unroll
            for (int q = 0; q < 8; q++) S += s[q] * __expf(m[q] - M);
            float I = 1.0f / S;
#pragma unroll
            for (int q = 0; q < 8; q++) alpha[tid*8 + q] = __expf(m[q] - M) * I;
        }
        __syncthreads();
        const __half* Pb = pp + (size_t)bh*NL*NL + (size_t)q0*NL;
        float* Ab = attn + (size_t)bh*NL*NL + (size_t)q0*NL;
#pragma unroll 4
        for (int it = 0; it < 128; it++) {
            int j = it*256 + tid;
            int r = j >> 8, c4 = j & 255;           // c4: float4 index in row
            uint2 u = __ldcs((const uint2*)(Pb + (size_t)r*NL + c4*4));
            float a = alpha[r*8 + (c4 >> 5)];
            __half2 h0 = *(__half2*)&u.x, h1 = *(__half2*)&u.y;
            float4 o = make_float4(__low2float(h0)*a, __high2float(h0)*a,
                                   __low2float(h1)*a, __high2float(h1)*a);
            __stcs((float4*)(Ab + (size_t)r*NL + c4*4), o);
        }
        return;
    }

    // ---- output GEMM block ----
    FRAG_COORDS();
    uint32_t smu = s2u(smc);
    const int m0 = (bid >> 3) * 128, n0 = (bid & 7) * 128;

    float acc[4][4][4] = {};
    const int lr_ = tid >> 3, lc_ = tid & 7;

#define LOAD_STAGE(i) do {                                                 \
        if ((i) < 16) {                                                    \
            int k0 = (i) * 64; uint32_t sb = smu + ((i) % NSTG)*2*128*BP_BIG; \
            _Pragma("unroll")                                              \
            for (int it = 0; it < 4; it++) {                               \
                int r = lr_ + it*32;                                       \
                cpa16(sb + r*BP_BIG + lc_*16, A  + (size_t)(m0+r)*1024 + k0 + lc_*8); \
                cpa16(sb + 128*BP_BIG + r*BP_BIG + lc_*16, BT + (size_t)(n0+r)*1024 + k0 + lc_*8); \
            }                                                              \
        }                                                                  \
        asm volatile("cp.async.commit_group;" ::: "memory");               \
    } while (0)

    LOAD_STAGE(0);
    LOAD_STAGE(1);
    for (int i = 0; i < 16; i++) {
        uint32_t sb = smu + (i % NSTG)*2*128*BP_BIG;
        asm volatile("cp.async.wait_group 1;" ::: "memory");
        __syncthreads();
        LOAD_STAGE(i + 2);
        warp_mma_h<4,2,4,BP_BIG,BP_BIG>(sb + (wm*64 + rF)*BP_BIG + cF,
                                        sb + 128*BP_BIG + (wn*32 + rF)*BP_BIG + cF, acc);
    }
#undef LOAD_STAGE

#pragma unroll
    for (int mi = 0; mi < 4; mi++)
#pragma unroll
        for (int ni = 0; ni < 4; ni++) {
            int mrow = m0 + wm*64 + mi*16 + g;
            int ncol = n0 + wn*32 + ni*8 + t*2;
            float b0 = bias[ncol], b1 = bias[ncol+1];
            *(float2*)(C + (size_t)mrow*1024 + ncol) =
                make_float2(acc[mi][ni][0] + b0, acc[mi][ni][1] + b1);
            *(float2*)(C + (size_t)(mrow+8)*1024 + ncol) =
                make_float2(acc[mi][ni][2] + b0, acc[mi][ni][3] + b1);
        }
}

// ============================================================
// mma_score: p' = fp16(exp(s - m_tile)) -> pp; partials (m_tile, sum)
// ============================================================
__global__ void __launch_bounds__(256, 2) mma_score(
    const __half* __restrict__ qcat, const __half* __restrict__ kcat,
    __half* __restrict__ pp, float* __restrict__ pmax, float* __restrict__ psum)
{
    extern __shared__ char smc[];
    float* smf = (float*)smc;
    const int tid = threadIdx.x;
    FRAG_COORDS();
    uint32_t smu = s2u(smc);
    const int bh = blockIdx.z;
    const int q0 = blockIdx.y * 128, n0 = blockIdx.x * 128;
    const __half* Ab = qcat + (size_t)bh*NL*192 + (size_t)q0*192;
    const __half* Bb = kcat + (size_t)bh*NL*192 + (size_t)n0*192;

    float acc[4][4][4] = {};
    const int lr_ = tid >> 3, lc_ = tid & 7;

#define LOAD_STAGE_S(i) do {                                               \
        if ((i) < 3) {                                                     \
            int k0 = (i) * 64; uint32_t sb = smu + ((i) % NSTG)*2*128*BP_BIG; \
            _Pragma("unroll")                                              \
            for (int it = 0; it < 4; it++) {                               \
                int r = lr_ + it*32;                                       \
                cpa16(sb + r*BP_BIG + lc_*16, Ab + (size_t)r*192 + k0 + lc_*8); \
                cpa16(sb + 128*BP_BIG + r*BP_BIG + lc_*16, Bb + (size_t)r*192 + k0 + lc_*8); \
            }                                                              \
        }                                                                  \
        asm volatile("cp.async.commit_group;" ::: "memory");               \
    } while (0)

    LOAD_STAGE_S(0);
    LOAD_STAGE_S(1);
    for (int i = 0; i < 3; i++) {
        uint32_t sb = smu + (i % NSTG)*2*128*BP_BIG;
        asm volatile("cp.async.wait_group 1;" ::: "memory");
        __syncthreads();
        LOAD_STAGE_S(i + 2);
        warp_mma_h<4,2,4,BP_BIG,BP_BIG>(sb + (wm*64 + rF)*BP_BIG + cF,
                                        sb + 128*BP_BIG + (wn*32 + rF)*BP_BIG + cF, acc);
    }
#undef LOAD_STAGE_S

    __syncthreads();
    const float sc = 1.0f / 24.0f;
    float* pm = smf;            // [128][4]
    float* ps = smf + 512;      // [128][4]
    float* mt = smf + 1024;     // [128]

#pragma unroll
    for (int mi = 0; mi < 4; mi++)
#pragma unroll
        for (int half = 0; half < 2; half++) {
            float mx = -1e30f;
#pragma unroll
            for (int ni = 0; ni < 4; ni++) {
                mx = fmaxf(mx, acc[mi][ni][half*2+0]);
                mx = fmaxf(mx, acc[mi][ni][half*2+1]);
            }
            mx = fmaxf(mx, __shfl_xor_sync(0xffffffffu, mx, 1));
            mx = fmaxf(mx, __shfl_xor_sync(0xffffffffu, mx, 2));
            if (t == 0) pm[(wm*64 + mi*16 + half*8 + g)*4 + wn] = mx * sc;
        }
    __syncthreads();
    if (tid < 128) {
        float M = pm[tid*4];
#pragma unroll
        for (int q = 1; q < 4; q++) M = fmaxf(M, pm[tid*4+q]);
        mt[tid] = M;
        pmax[((size_t)bh*NL + q0 + tid)*8 + blockIdx.x] = M;
    }
    __syncthreads();

#pragma unroll
    for (int mi = 0; mi < 4; mi++)
#pragma unroll
        for (int half = 0; half < 2; half++) {
            int lr = wm*64 + mi*16 + half*8 + g;
            int mrow = q0 + lr;
            float M = mt[lr];
            float se = 0.f;
            __half* dst = pp + ((size_t)bh*NL + mrow)*NL + n0 + wn*32 + t*2;
#pragma unroll
            for (int ni = 0; ni < 4; ni++) {
                float e0 = __expf(acc[mi][ni][half*2+0]*sc - M);
                float e1 = __expf(acc[mi][ni][half*2+1]*sc - M);
                __half2 h = __floats2half2_rn(e0, e1);
                *(__half2*)(dst + ni*8) = h;
                se += __half2float(__low2half(h)) + __half2float(__high2half(h));
            }
            se += __shfl_xor_sync(0xffffffffu, se, 1);
            se += __shfl_xor_sync(0xffffffffu, se, 2);
            if (t == 0) ps[lr*4 + wn] = se;
        }
    __syncthreads();
    if (tid < 128) {
        float S = ps[tid*4] + ps[tid*4+1] + ps[tid*4+2] + ps[tid*4+3];
        psum[((size_t)bh*NL + q0 + tid)*8 + blockIdx.x] = S;
    }
}

// ============================================================
// mma_ctx: BK=32, 3 CTAs/SM, NO attn write (moved to writer blocks).
// stage (15360 B): [Ph 128*80][Vh 64*80]; alpha[128][8] after stages.
// ============================================================
__global__ void __launch_bounds__(256, 3) mma_ctx(
    const __half* __restrict__ pp, const __half* __restrict__ vt,
    const float* __restrict__ pmax, const float* __restrict__ psum,
    __half* __restrict__ ctx)
{
    extern __shared__ char smc[];
    const int tid = threadIdx.x;
    FRAG_COORDS();
    uint32_t smu = s2u(smc);
    float* alpha = (float*)(smc + NSTG*15360);    // [128][8]
    const int bh = blockIdx.y, q0 = blockIdx.x * 128;
    const __half* Pb = pp + (size_t)bh*NL*NL + (size_t)q0*NL;
    const __half* Bb = vt + (size_t)bh*64*NL;

    if (tid < 128) {
        size_t row = (size_t)bh*NL + q0 + tid;
        float m[8], s[8];
#pragma unroll
        for (int q = 0; q < 8; q++) { m[q] = pmax[row*8+q]; s[q] = psum[row*8+q]; }
        float M = m[0];
#pragma unroll
        for (int q = 1; q < 8; q++) M = fmaxf(M, m[q]);
        float S = 0.f;
#pragma unroll
        for (int q = 0; q < 8; q++) S += s[q] * __expf(m[q] - M);
        float I = 1.0f / S;
#pragma unroll
        for (int q = 0; q < 8; q++) alpha[tid*8 + q] = __expf(m[q] - M) * I;
    }

    float acc[4][2][4] = {};
    const int pr_ = tid >> 2, pc_ = tid & 3;

#define LOAD_STAGE_C(i) do {                                               \
        if ((i) < 32) {                                                    \
            int k0 = (i) * 32; uint32_t sb = smu + ((i) % NSTG)*15360;      \
            _Pragma("unroll")                                              \
            for (int it = 0; it < 2; it++) {                               \
                int r = pr_ + it*64;                                       \
                cpa16(sb + r*BP_CTX + pc_*16, Pb + (size_t)r*NL + k0 + pc_*8); \
            }                                                              \
            cpa16(sb + 128*BP_CTX + pr_*BP_CTX + pc_*16, Bb + (size_t)pr_*NL + k0 + pc_*8); \
        }                                                                  \
        asm volatile("cp.async.commit_group;" ::: "memory");               \
    } while (0)

    LOAD_STAGE_C(0);
    LOAD_STAGE_C(1);
    for (int i = 0; i < 32; i++) {
        uint32_t sb = smu + (i % NSTG)*15360;
        char* ph = smc + (i % NSTG)*15360;
        asm volatile("cp.async.wait_group 1;" ::: "memory");
        __syncthreads();
        LOAD_STAGE_C(i + 2);
        // transform in smem only: p_norm = float(p')*alpha -> fp16
        {
            int tl = i >> 2;
#pragma unroll
            for (int it = 0; it < 4; it++) {
                int j = it*256 + tid;
                int r = j >> 3, c4 = j & 7;          // 4-half unit
                uint32_t* hp = (uint32_t*)(ph + r*BP_CTX + c4*8);
                uint32_t u0 = hp[0], u1 = hp[1];
                float a = alpha[r*8 + tl];
                __half2 h0 = *(__half2*)&u0, h1 = *(__half2*)&u1;
                float4 o = make_float4(__low2float(h0)*a, __high2float(h0)*a,
                                       __low2float(h1)*a, __high2float(h1)*a);
                __half2 n0 = __floats2half2_rn(o.x, o.y);
                __half2 n1 = __floats2half2_rn(o.z, o.w);
                hp[0] = *(uint32_t*)&n0;
                hp[1] = *(uint32_t*)&n1;
            }
        }
        __syncthreads();
        warp_mma_h<4,1,2,BP_CTX,BP_CTX>(sb + (wm*64 + rF)*BP_CTX + cF,
                                        sb + 128*BP_CTX + (wn*16 + rF)*BP_CTX + cF, acc);
    }
#undef LOAD_STAGE_C

    const int b = bh >> 4, hh = bh & 15;
#pragma unroll
    for (int mi = 0; mi < 4; mi++)
#pragma unroll
        for (int ni = 0; ni < 2; ni++) {
            int mrow = q0 + wm*64 + mi*16 + g;
            int ncol = wn*16 + ni*8 + t*2;
            size_t r0 = ((size_t)(b*1024 + mrow))*1024 + hh*64 + ncol;
            size_t r1 = ((size_t)(b*1024 + mrow + 8))*1024 + hh*64 + ncol;
            *(__half2*)(ctx + r0) = __floats2half2_rn(acc[mi][ni][0], acc[mi][ni][1]);
            *(__half2*)(ctx + r1) = __floats2half2_rn(acc[mi][ni][2], acc[mi][ni][3]);
        }
}

// ============================================================
// launch
// ============================================================
extern "C" void kernel_launch(void* const* d_in, const int* in_sizes, int n_in,
                              void* d_out, int out_size)
{
    const float* query = (const float*)d_in[0];
    const float* key   = (const float*)d_in[1];
    const float* value = (const float*)d_in[2];
    const int*   pc    = (const int*)d_in[3];
    const int*   bon   = (const int*)d_in[4];
    const float* Wpq = (const float*)d_in[5],  *bpq = (const float*)d_in[6];
    const float* Whq = (const float*)d_in[7],  *bhq = (const float*)d_in[8];
    const float* Wvq = (const float*)d_in[9],  *bvq = (const float*)d_in[10];
    const float* Wk  = (const float*)d_in[11], *bk  = (const float*)d_in[12];
    const float* Wv  = (const float*)d_in[13], *bv  = (const float*)d_in[14];
    const float* Wc  = (const float*)d_in[15], *bc  = (const float*)d_in[16];
    const float* Wb  = (const float*)d_in[17], *bb  = (const float*)d_in[18];
    const float* Wo  = (const float*)d_in[19], *bo  = (const float*)d_in[20];

    __half *qcat_p, *kcat_p, *vt_p, *ctx_p, *wt_p, *qh_p, *kh_p, *vh_p, *pp_p;
    float *bcat_p, *pmax_p, *psum_p;
    cudaGetSymbolAddress((void**)&qcat_p, g_qcat);
    cudaGetSymbolAddress((void**)&kcat_p, g_kcat);
    cudaGetSymbolAddress((void**)&vt_p,   g_vt);
    cudaGetSymbolAddress((void**)&ctx_p,  g_ctx);
    cudaGetSymbolAddress((void**)&wt_p,   g_wt);
    cudaGetSymbolAddress((void**)&qh_p,   g_qh);
    cudaGetSymbolAddress((void**)&kh_p,   g_kh);
    cudaGetSymbolAddress((void**)&vh_p,   g_vh);
    cudaGetSymbolAddress((void**)&pp_p,   g_pp);
    cudaGetSymbolAddress((void**)&bcat_p, g_bcat);
    cudaGetSymbolAddress((void**)&pmax_p, g_pmax);
    cudaGetSymbolAddress((void**)&psum_p, g_psum);

    __half* WqcatT = wt_p;
    __half* WkT    = wt_p + 3u*1024u*1024u;
    __half* WvT    = wt_p + 4u*1024u*1024u;
    __half* WoT    = wt_p + 5u*1024u*1024u;

    float* out  = (float*)d_out;
    float* attn = out + (size_t)NB * NL * ND;

    const int SM_BIG = NSTG * 2 * 128 * BP_BIG;          // 110592
    const int SM_CTX = NSTG * 15360 + 4096;              // 50176
    cudaFuncSetAttribute(mma_proj,      cudaFuncAttributeMaxDynamicSharedMemorySize, SM_BIG);
    cudaFuncSetAttribute(mma_out_fused, cudaFuncAttributeMaxDynamicSharedMemorySize, SM_BIG);
    cudaFuncSetAttribute(mma_score,     cudaFuncAttributeMaxDynamicSharedMemorySize, SM_BIG);
    cudaFuncSetAttribute(mma_ctx,       cudaFuncAttributeMaxDynamicSharedMemorySize, SM_CTX);

    ProArgs pr;
    pr.q = (const float4*)query; pr.k = (const float4*)key; pr.v = (const float4*)value;
    pr.qh = (__half2*)qh_p; pr.kh = (__half2*)kh_p; pr.vh = (__half2*)vh_p;
    pr.wsrc[0] = Wpq; pr.wdst[0] = WqcatT + 0u*1024u*1024u;
    pr.wsrc[1] = Whq; pr.wdst[1] = WqcatT + 1u*1024u*1024u;
    pr.wsrc[2] = Wvq; pr.wdst[2] = WqcatT + 2u*1024u*1024u;
    pr.wsrc[3] = Wk;  pr.wdst[3] = WkT;
    pr.wsrc[4] = Wv;  pr.wdst[4] = WvT;
    pr.wsrc[5] = Wo;  pr.wdst[5] = WoT;
    pr.pc = pc; pr.bon = bon; pr.Wc = Wc; pr.bcW = bc; pr.Wb = Wb; pr.bbW = bb;
    pr.kcat = kcat_p;
    pr.bpq = bpq; pr.bhq = bhq; pr.bvq = bvq; pr.bcat = bcat_p;
    prologue<<<22540, 256>>>(pr);

    ProjArgs pa;
    pa.Aq = qh_p; pa.Ak = kh_p; pa.Av = vh_p;
    pa.Wq = WqcatT; pa.Wk = WkT; pa.Wv = WvT;
    pa.bq = bcat_p; pa.bk = bk; pa.bv = bv;
    pa.Cq = qcat_p; pa.Ck = kcat_p; pa.Cv = vt_p;
    mma_proj<<<dim3(40, 32), 256, SM_BIG>>>(pa);

    mma_score<<<dim3(8, 8, NBH), 256, SM_BIG>>>(qcat_p, kcat_p, pp_p, pmax_p, psum_p);
    mma_ctx<<<dim3(8, NBH), 256, SM_CTX>>>(pp_p, vt_p, pmax_p, psum_p, ctx_p);
    mma_out_fused<<<768, 256, SM_BIG>>>(ctx_p, WoT, bo, out, pp_p, pmax_p, psum_p, attn);
}

// round 17
// speedup vs baseline: 1.2799x; 1.2799x over previous
#include <cuda_runtime.h>
#include <cuda_fp16.h>
#include <math.h>
#include <cstdint>

#define NB 4
#define NL 1024
#define ND 1024
#define NH 16
#define NHD 64
#define NBH (NB*NH)

// ---------------- scratch (device globals) ----------------
__device__ __align__(16) __half g_qcat[NBH*NL*192];     // [bh][l][pq|hq|vq]
__device__ __align__(16) __half g_kcat[NBH*NL*192];     // [bh][l][k|cf|bf]
__device__ __align__(16) __half g_vt[NBH*NHD*NL];       // [bh][hd][l]
__device__ __align__(16) __half g_ctx[NB*NL*ND];
__device__ __align__(16) __half g_pp[(size_t)NBH*NL*NL]; // fp16 exp(s - m_tile)
__device__ __align__(16) __half g_wt[6u*1024u*1024u];
__device__ __align__(16) __half g_qh[NB*NL*ND];
__device__ __align__(16) __half g_kh[NB*NL*ND];
__device__ __align__(16) __half g_vh[NB*NL*ND];
__device__ __align__(16) float  g_bcat[3072];
__device__ __align__(16) float  g_pmax[NBH*NL*8];
__device__ __align__(16) float  g_psum[NBH*NL*8];

// ---------------- helpers ----------------
__device__ __forceinline__ void cpa16(uint32_t s, const void* g) {
    asm volatile("cp.async.cg.shared.global [%0], [%1], 16;" :: "r"(s), "l"(g) : "memory");
}
__device__ __forceinline__ uint32_t s2u(const void* p) {
    return (uint32_t)__cvta_generic_to_shared(p);
}
__device__ __forceinline__ void ldsm4(uint32_t (&r)[4], uint32_t a) {
    asm volatile("ldmatrix.sync.aligned.m8n8.x4.shared.b16 {%0,%1,%2,%3}, [%4];"
        : "=r"(r[0]), "=r"(r[1]), "=r"(r[2]), "=r"(r[3]) : "r"(a));
}
__device__ __forceinline__ void mma16816(float (&d)[4], const uint32_t (&a)[4], uint32_t b0, uint32_t b1) {
    asm volatile(
        "mma.sync.aligned.m16n8k16.row.col.f32.f16.f16.f32 "
        "{%0,%1,%2,%3}, {%4,%5,%6,%7}, {%8,%9}, {%0,%1,%2,%3};"
        : "+f"(d[0]), "+f"(d[1]), "+f"(d[2]), "+f"(d[3])
        : "r"(a[0]), "r"(a[1]), "r"(a[2]), "r"(a[3]), "r"(b0), "r"(b1));
}

#define BP_BIG 144    // byte pitch, rows of 64 fp16
#define BP_CTX 80     // byte pitch, rows of 32 fp16
#define NSTG 3

template<int MSUB, int NB16, int KSTEPS, int AP, int BPP>
__device__ __forceinline__ void warp_mma_h(
    uint32_t aBase, uint32_t bBase, float (&acc)[MSUB][NB16*2][4])
{
#pragma unroll
    for (int ks = 0; ks < KSTEPS; ks++) {
        uint32_t a[MSUB][4];
#pragma unroll
        for (int mi = 0; mi < MSUB; mi++)
            ldsm4(a[mi], aBase + mi*16*AP + ks*32);
        uint32_t b[NB16*2][2];
#pragma unroll
        for (int nj = 0; nj < NB16; nj++) {
            uint32_t r[4];
            ldsm4(r, bBase + nj*16*BPP + ks*32);
            b[2*nj+0][0] = r[0]; b[2*nj+0][1] = r[2];
            b[2*nj+1][0] = r[1]; b[2*nj+1][1] = r[3];
        }
#pragma unroll
        for (int mi = 0; mi < MSUB; mi++)
#pragma unroll
            for (int ni = 0; ni < NB16*2; ni++)
                mma16816(acc[mi][ni], a[mi], b[ni][0], b[ni][1]);
    }
}

#define LAY_QCAT 0
#define LAY_KCAT 1
#define LAY_VT   2

#define FRAG_COORDS()                                                   \
    const int lane = tid & 31, wid = tid >> 5;                          \
    const int wm = wid & 1, wn = wid >> 1;                              \
    const int g = lane >> 2, t = lane & 3;                              \
    const int rF = (lane & 7) + ((lane >> 3) & 1)*8;                    \
    const int cF = (lane >> 4) * 16

// ============================================================
// prologue: ONE launch = convert3 | transpose6 | chordfeat | concat
// ============================================================
struct ProArgs {
    const float4 *q, *k, *v;
    __half2 *qh, *kh, *vh;
    const float* wsrc[6];
    __half* wdst[6];
    const int *pc, *bon;
    const float *Wc, *bcW, *Wb, *bbW;
    __half* kcat;
    const float *bpq, *bhq, *bvq;
    float* bcat;
};

__global__ void __launch_bounds__(256) prologue(ProArgs p)
{
    __shared__ float tbuf[32][33];
    const int bid = blockIdx.x, tid = threadIdx.x;

    if (bid < 12288) {
        int i = bid*256 + tid;
        int seg = i >> 20, j = i & 1048575;
        const float4* in = (seg == 0) ? p.q : (seg == 1) ? p.k : p.v;
        __half2* out = (seg == 0) ? p.qh : (seg == 1) ? p.kh : p.vh;
        float4 x = in[j];
        out[j*2]   = __floats2half2_rn(x.x, x.y);
        out[j*2+1] = __floats2half2_rn(x.z, x.w);
    } else if (bid < 18432) {
        int w = bid - 12288;
        int z = w >> 10, tile = w & 1023;
        const float* src = p.wsrc[z];
        __half* dst = p.wdst[z];
        int bx = (tile & 31) * 32, by = (tile >> 5) * 32;
        int x = tid & 31, y0 = tid >> 5;
#pragma unroll
        for (int dy = 0; dy < 32; dy += 8)
            tbuf[y0+dy][x] = src[(size_t)(by + y0 + dy)*1024 + bx + x];
        __syncthreads();
#pragma unroll
        for (int dy = 0; dy < 32; dy += 8)
            dst[(size_t)(bx + y0 + dy)*1024 + by + x] = __float2half_rn(tbuf[x][y0+dy]);
    } else if (bid < 22528) {
        int idx = (bid - 18432)*256 + tid;
        int l = idx >> 10, n = idx & 1023;
        float sc = p.bcW[n], sb = p.bbW[n];
#pragma unroll
        for (int q = 0; q < 12; q++) {
            sc += (float)p.pc[l*12 + q] * p.Wc[q*1024 + n];
            sb += (float)p.bon[l*12 + q] * p.Wb[q*1024 + n];
        }
        __half hc = __float2half_rn(sc), hb = __float2half_rn(sb);
        int h = n >> 6, hd = n & 63;
#pragma unroll
        for (int b = 0; b < 4; b++) {
            size_t row = ((size_t)((b*16 + h)*1024 + l))*192;
            p.kcat[row + 64 + hd]  = hc;
            p.kcat[row + 128 + hd] = hb;
        }
    } else {
        int i = (bid - 22528)*256 + tid;
        p.bcat[i] = (i < 1024) ? p.bpq[i] : (i < 2048) ? p.bhq[i - 1024] : p.bvq[i - 2048];
    }
}

// ============================================================
// mma_proj: 3 projection GEMMs; 256 thr, warp tile 64x32, BK=64
// ============================================================
struct ProjArgs {
    const __half* Aq; const __half* Ak; const __half* Av;
    const __half* Wq; const __half* Wk; const __half* Wv;
    const float* bq; const float* bk; const float* bv;
    __half* Cq; __half* Ck; __half* Cv;
};

__global__ void __launch_bounds__(256, 2) mma_proj(ProjArgs p)
{
    extern __shared__ char smc[];
    const int tid = threadIdx.x;
    FRAG_COORDS();
    uint32_t smu = s2u(smc);
    const int nb = blockIdx.x, m0 = blockIdx.y * 128;

    const __half *A, *BT; const float* bias; __half* C; int n0, lay;
    if (nb < 24)      { A = p.Aq; BT = p.Wq; bias = p.bq; C = p.Cq; n0 = nb*128;      lay = LAY_QCAT; }
    else if (nb < 32) { A = p.Ak; BT = p.Wk; bias = p.bk; C = p.Ck; n0 = (nb-24)*128; lay = LAY_KCAT; }
    else              { A = p.Av; BT = p.Wv; bias = p.bv; C = p.Cv; n0 = (nb-32)*128; lay = LAY_VT; }

    float acc[4][4][4] = {};
    const int lr_ = tid >> 3, lc_ = tid & 7;

#define LOAD_STAGE(i) do {                                                 \
        if ((i) < 16) {                                                    \
            int k0 = (i) * 64; uint32_t sb = smu + ((i) % NSTG)*2*128*BP_BIG; \
            _Pragma("unroll")                                              \
            for (int it = 0; it < 4; it++) {                               \
                int r = lr_ + it*32;                                       \
                cpa16(sb + r*BP_BIG + lc_*16, A  + (size_t)(m0+r)*1024 + k0 + lc_*8); \
                cpa16(sb + 128*BP_BIG + r*BP_BIG + lc_*16, BT + (size_t)(n0+r)*1024 + k0 + lc_*8); \
            }                                                              \
        }                                                                  \
        asm volatile("cp.async.commit_group;" ::: "memory");               \
    } while (0)

    LOAD_STAGE(0);
    LOAD_STAGE(1);
    for (int i = 0; i < 16; i++) {
        uint32_t sb = smu + (i % NSTG)*2*128*BP_BIG;
        asm volatile("cp.async.wait_group 1;" ::: "memory");
        __syncthreads();
        LOAD_STAGE(i + 2);
        warp_mma_h<4,2,4,BP_BIG,BP_BIG>(sb + (wm*64 + rF)*BP_BIG + cF,
                                        sb + 128*BP_BIG + (wn*32 + rF)*BP_BIG + cF, acc);
    }
#undef LOAD_STAGE

#pragma unroll
    for (int mi = 0; mi < 4; mi++)
#pragma unroll
        for (int ni = 0; ni < 4; ni++) {
            int mrow = m0 + wm*64 + mi*16 + g;
            int ncol = n0 + wn*32 + ni*8 + t*2;
            float b0 = bias[ncol], b1 = bias[ncol+1];
            float v00 = acc[mi][ni][0] + b0, v01 = acc[mi][ni][1] + b1;
            float v10 = acc[mi][ni][2] + b0, v11 = acc[mi][ni][3] + b1;
            int b = mrow >> 10, l = mrow & 1023;
            if (lay == LAY_VT) {
                int h = ncol >> 6, hd = ncol & 63;
                size_t base = ((size_t)((b*16 + h)*64 + hd)) * NL;
                C[base + l]          = __float2half_rn(v00);
                C[base + l + 8]      = __float2half_rn(v10);
                C[base + NL + l]     = __float2half_rn(v01);
                C[base + NL + l + 8] = __float2half_rn(v11);
            } else {
                int seg, nn;
                if (lay == LAY_QCAT) { seg = ncol >> 10; nn = ncol & 1023; }
                else                 { seg = 0;          nn = ncol; }
                int h = nn >> 6, hd = nn & 63;
                size_t r0 = ((size_t)((b*16 + h)*1024 + l))*192 + seg*64 + hd;
                size_t r1 = ((size_t)((b*16 + h)*1024 + l + 8))*192 + seg*64 + hd;
                *(__half2*)(C + r0) = __floats2half2_rn(v00, v01);
                *(__half2*)(C + r1) = __floats2half2_rn(v10, v11);
            }
        }
}

// ============================================================
// mma_out: out(f32) = ctx(f16) @ WoT^T + bias; BK=64
// ============================================================
__global__ void __launch_bounds__(256, 2) mma_out(
    const __half* __restrict__ A, const __half* __restrict__ BT,
    const float* __restrict__ bias, float* __restrict__ C)
{
    extern __shared__ char smc[];
    const int tid = threadIdx.x;
    FRAG_COORDS();
    uint32_t smu = s2u(smc);
    const int m0 = blockIdx.y * 128, n0 = blockIdx.x * 128;

    float acc[4][4][4] = {};
    const int lr_ = tid >> 3, lc_ = tid & 7;

#define LOAD_STAGE(i) do {                                                 \
        if ((i) < 16) {                                                    \
            int k0 = (i) * 64; uint32_t sb = smu + ((i) % NSTG)*2*128*BP_BIG; \
            _Pragma("unroll")                                              \
            for (int it = 0; it < 4; it++) {                               \
                int r = lr_ + it*32;                                       \
                cpa16(sb + r*BP_BIG + lc_*16, A  + (size_t)(m0+r)*1024 + k0 + lc_*8); \
                cpa16(sb + 128*BP_BIG + r*BP_BIG + lc_*16, BT + (size_t)(n0+r)*1024 + k0 + lc_*8); \
            }                                                              \
        }                                                                  \
        asm volatile("cp.async.commit_group;" ::: "memory");               \
    } while (0)

    LOAD_STAGE(0);
    LOAD_STAGE(1);
    for (int i = 0; i < 16; i++) {
        uint32_t sb = smu + (i % NSTG)*2*128*BP_BIG;
        asm volatile("cp.async.wait_group 1;" ::: "memory");
        __syncthreads();
        LOAD_STAGE(i + 2);
        warp_mma_h<4,2,4,BP_BIG,BP_BIG>(sb + (wm*64 + rF)*BP_BIG + cF,
                                        sb + 128*BP_BIG + (wn*32 + rF)*BP_BIG + cF, acc);
    }
#undef LOAD_STAGE

#pragma unroll
    for (int mi = 0; mi < 4; mi++)
#pragma unroll
        for (int ni = 0; ni < 4; ni++) {
            int mrow = m0 + wm*64 + mi*16 + g;
            int ncol = n0 + wn*32 + ni*8 + t*2;
            float b0 = bias[ncol], b1 = bias[ncol+1];
            *(float2*)(C + (size_t)mrow*1024 + ncol) =
                make_float2(acc[mi][ni][0] + b0, acc[mi][ni][1] + b1);
            *(float2*)(C + (size_t)(mrow+8)*1024 + ncol) =
                make_float2(acc[mi][ni][2] + b0, acc[mi][ni][3] + b1);
        }
}

// ============================================================
// mma_score: p' = fp16(exp(s - m_tile)) -> pp; partials (m_tile, sum)
// ============================================================
__global__ void __launch_bounds__(256, 2) mma_score(
    const __half* __restrict__ qcat, const __half* __restrict__ kcat,
    __half* __restrict__ pp, float* __restrict__ pmax, float* __restrict__ psum)
{
    extern __shared__ char smc[];
    float* smf = (float*)smc;
    const int tid = threadIdx.x;
    FRAG_COORDS();
    uint32_t smu = s2u(smc);
    const int bh = blockIdx.z;
    const int q0 = blockIdx.y * 128, n0 = blockIdx.x * 128;
    const __half* Ab = qcat + (size_t)bh*NL*192 + (size_t)q0*192;
    const __half* Bb = kcat + (size_t)bh*NL*192 + (size_t)n0*192;

    float acc[4][4][4] = {};
    const int lr_ = tid >> 3, lc_ = tid & 7;

#define LOAD_STAGE_S(i) do {                                               \
        if ((i) < 3) {                                                     \
            int k0 = (i) * 64; uint32_t sb = smu + ((i) % NSTG)*2*128*BP_BIG; \
            _Pragma("unroll")                                              \
            for (int it = 0; it < 4; it++) {                               \
                int r = lr_ + it*32;                                       \
                cpa16(sb + r*BP_BIG + lc_*16, Ab + (size_t)r*192 + k0 + lc_*8); \
                cpa16(sb + 128*BP_BIG + r*BP_BIG + lc_*16, Bb + (size_t)r*192 + k0 + lc_*8); \
            }                                                              \
        }                                                                  \
        asm volatile("cp.async.commit_group;" ::: "memory");               \
    } while (0)

    LOAD_STAGE_S(0);
    LOAD_STAGE_S(1);
    for (int i = 0; i < 3; i++) {
        uint32_t sb = smu + (i % NSTG)*2*128*BP_BIG;
        asm volatile("cp.async.wait_group 1;" ::: "memory");
        __syncthreads();
        LOAD_STAGE_S(i + 2);
        warp_mma_h<4,2,4,BP_BIG,BP_BIG>(sb + (wm*64 + rF)*BP_BIG + cF,
                                        sb + 128*BP_BIG + (wn*32 + rF)*BP_BIG + cF, acc);
    }
#undef LOAD_STAGE_S

    __syncthreads();
    const float sc = 1.0f / 24.0f;
    float* pm = smf;            // [128][4]
    float* ps = smf + 512;      // [128][4]
    float* mt = smf + 1024;     // [128]

#pragma unroll
    for (int mi = 0; mi < 4; mi++)
#pragma unroll
        for (int half = 0; half < 2; half++) {
            float mx = -1e30f;
#pragma unroll
            for (int ni = 0; ni < 4; ni++) {
                mx = fmaxf(mx, acc[mi][ni][half*2+0]);
                mx = fmaxf(mx, acc[mi][ni][half*2+1]);
            }
            mx = fmaxf(mx, __shfl_xor_sync(0xffffffffu, mx, 1));
            mx = fmaxf(mx, __shfl_xor_sync(0xffffffffu, mx, 2));
            if (t == 0) pm[(wm*64 + mi*16 + half*8 + g)*4 + wn] = mx * sc;
        }
    __syncthreads();
    if (tid < 128) {
        float M = pm[tid*4];
#pragma unroll
        for (int q = 1; q < 4; q++) M = fmaxf(M, pm[tid*4+q]);
        mt[tid] = M;
        pmax[((size_t)bh*NL + q0 + tid)*8 + blockIdx.x] = M;
    }
    __syncthreads();

#pragma unroll
    for (int mi = 0; mi < 4; mi++)
#pragma unroll
        for (int half = 0; half < 2; half++) {
            int lr = wm*64 + mi*16 + half*8 + g;
            int mrow = q0 + lr;
            float M = mt[lr];
            float se = 0.f;
            __half* dst = pp + ((size_t)bh*NL + mrow)*NL + n0 + wn*32 + t*2;
#pragma unroll
            for (int ni = 0; ni < 4; ni++) {
                float e0 = __expf(acc[mi][ni][half*2+0]*sc - M);
                float e1 = __expf(acc[mi][ni][half*2+1]*sc - M);
                __half2 h = __floats2half2_rn(e0, e1);
                *(__half2*)(dst + ni*8) = h;
                se += __half2float(__low2half(h)) + __half2float(__high2half(h));
            }
            se += __shfl_xor_sync(0xffffffffu, se, 1);
            se += __shfl_xor_sync(0xffffffffu, se, 2);
            if (t == 0) ps[lr*4 + wn] = se;
        }
    __syncthreads();
    if (tid < 128) {
        float S = ps[tid*4] + ps[tid*4+1] + ps[tid*4+2] + ps[tid*4+3];
        psum[((size_t)bh*NL + q0 + tid)*8 + blockIdx.x] = S;
    }
}

// ============================================================
// mma_ctx: BK=32, 3 CTAs/SM, float4 streaming attn stores (__stcs).
// stage (15360 B): [Ph 128*80][Vh 64*80]; alpha[128][8] after stages.
// ============================================================
__global__ void __launch_bounds__(256, 3) mma_ctx(
    const __half* __restrict__ pp, const __half* __restrict__ vt,
    const float* __restrict__ pmax, const float* __restrict__ psum,
    float* __restrict__ attn, __half* __restrict__ ctx)
{
    extern __shared__ char smc[];
    const int tid = threadIdx.x;
    FRAG_COORDS();
    uint32_t smu = s2u(smc);
    float* alpha = (float*)(smc + NSTG*15360);    // [128][8]
    const int bh = blockIdx.y, q0 = blockIdx.x * 128;
    const __half* Pb = pp + (size_t)bh*NL*NL + (size_t)q0*NL;
    const __half* Bb = vt + (size_t)bh*64*NL;
    float* Ab = attn + (size_t)bh*NL*NL + (size_t)q0*NL;

    if (tid < 128) {
        size_t row = (size_t)bh*NL + q0 + tid;
        float m[8], s[8];
#pragma unroll
        for (int q = 0; q < 8; q++) { m[q] = pmax[row*8+q]; s[q] = psum[row*8+q]; }
        float M = m[0];
#pragma unroll
        for (int q = 1; q < 8; q++) M = fmaxf(M, m[q]);
        float S = 0.f;
#pragma unroll
        for (int q = 0; q < 8; q++) S += s[q] * __expf(m[q] - M);
        float I = 1.0f / S;
#pragma unroll
        for (int q = 0; q < 8; q++) alpha[tid*8 + q] = __expf(m[q] - M) * I;
    }

    float acc[4][2][4] = {};
    const int pr_ = tid >> 2, pc_ = tid & 3;

#define LOAD_STAGE_C(i) do {                                               \
        if ((i) < 32) {                                                    \
            int k0 = (i) * 32; uint32_t sb = smu + ((i) % NSTG)*15360;      \
            _Pragma("unroll")                                              \
            for (int it = 0; it < 2; it++) {                               \
                int r = pr_ + it*64;                                       \
                cpa16(sb + r*BP_CTX + pc_*16, Pb + (size_t)r*NL + k0 + pc_*8); \
            }                                                              \
            cpa16(sb + 128*BP_CTX + pr_*BP_CTX + pc_*16, Bb + (size_t)pr_*NL + k0 + pc_*8); \
        }                                                                  \
        asm volatile("cp.async.commit_group;" ::: "memory");               \
    } while (0)

    LOAD_STAGE_C(0);
    LOAD_STAGE_C(1);
    for (int i = 0; i < 32; i++) {
        uint32_t sb = smu + (i % NSTG)*15360;
        char* ph = smc + (i % NSTG)*15360;
        asm volatile("cp.async.wait_group 1;" ::: "memory");
        __syncthreads();
        LOAD_STAGE_C(i + 2);
        // transform: 128x32 chunk; 8B smem units, streaming float4 attn stores
        {
            int k0 = i * 32, tl = i >> 2;
#pragma unroll
            for (int it = 0; it < 4; it++) {
                int j = it*256 + tid;
                int r = j >> 3, c4 = j & 7;          // 4-half unit
                uint32_t* hp = (uint32_t*)(ph + r*BP_CTX + c4*8);
                uint32_t u0 = hp[0], u1 = hp[1];
                float a = alpha[r*8 + tl];
                __half2 h0 = *(__half2*)&u0, h1 = *(__half2*)&u1;
                float4 o = make_float4(__low2float(h0)*a, __high2float(h0)*a,
                                       __low2float(h1)*a, __high2float(h1)*a);
                __stcs((float4*)(Ab + (size_t)r*NL + k0 + c4*4), o);
                __half2 n0 = __floats2half2_rn(o.x, o.y);
                __half2 n1 = __floats2half2_rn(o.z, o.w);
                hp[0] = *(uint32_t*)&n0;
                hp[1] = *(uint32_t*)&n1;
            }
        }
        __syncthreads();
        warp_mma_h<4,1,2,BP_CTX,BP_CTX>(sb + (wm*64 + rF)*BP_CTX + cF,
                                        sb + 128*BP_CTX + (wn*16 + rF)*BP_CTX + cF, acc);
    }
#undef LOAD_STAGE_C

    const int b = bh >> 4, hh = bh & 15;
#pragma unroll
    for (int mi = 0; mi < 4; mi++)
#pragma unroll
        for (int ni = 0; ni < 2; ni++) {
            int mrow = q0 + wm*64 + mi*16 + g;
            int ncol = wn*16 + ni*8 + t*2;
            size_t r0 = ((size_t)(b*1024 + mrow))*1024 + hh*64 + ncol;
            size_t r1 = ((size_t)(b*1024 + mrow + 8))*1024 + hh*64 + ncol;
            *(__half2*)(ctx + r0) = __floats2half2_rn(acc[mi][ni][0], acc[mi][ni][1]);
            *(__half2*)(ctx + r1) = __floats2half2_rn(acc[mi][ni][2], acc[mi][ni][3]);
        }
}

// ============================================================
// launch
// ============================================================
extern "C" void kernel_launch(void* const* d_in, const int* in_sizes, int n_in,
                              void* d_out, int out_size)
{
    const float* query = (const float*)d_in[0];
    const float* key   = (const float*)d_in[1];
    const float* value = (const float*)d_in[2];
    const int*   pc    = (const int*)d_in[3];
    const int*   bon   = (const int*)d_in[4];
    const float* Wpq = (const float*)d_in[5],  *bpq = (const float*)d_in[6];
    const float* Whq = (const float*)d_in[7],  *bhq = (const float*)d_in[8];
    const float* Wvq = (const float*)d_in[9],  *bvq = (const float*)d_in[10];
    const float* Wk  = (const float*)d_in[11], *bk  = (const float*)d_in[12];
    const float* Wv  = (const float*)d_in[13], *bv  = (const float*)d_in[14];
    const float* Wc  = (const float*)d_in[15], *bc  = (const float*)d_in[16];
    const float* Wb  = (const float*)d_in[17], *bb  = (const float*)d_in[18];
    const float* Wo  = (const float*)d_in[19], *bo  = (const float*)d_in[20];

    __half *qcat_p, *kcat_p, *vt_p, *ctx_p, *wt_p, *qh_p, *kh_p, *vh_p, *pp_p;
    float *bcat_p, *pmax_p, *psum_p;
    cudaGetSymbolAddress((void**)&qcat_p, g_qcat);
    cudaGetSymbolAddress((void**)&kcat_p, g_kcat);
    cudaGetSymbolAddress((void**)&vt_p,   g_vt);
    cudaGetSymbolAddress((void**)&ctx_p,  g_ctx);
    cudaGetSymbolAddress((void**)&wt_p,   g_wt);
    cudaGetSymbolAddress((void**)&qh_p,   g_qh);
    cudaGetSymbolAddress((void**)&kh_p,   g_kh);
    cudaGetSymbolAddress((void**)&vh_p,   g_vh);
    cudaGetSymbolAddress((void**)&pp_p,   g_pp);
    cudaGetSymbolAddress((void**)&bcat_p, g_bcat);
    cudaGetSymbolAddress((void**)&pmax_p, g_pmax);
    cudaGetSymbolAddress((void**)&psum_p, g_psum);

    __half* WqcatT = wt_p;
    __half* WkT    = wt_p + 3u*1024u*1024u;
    __half* WvT    = wt_p + 4u*1024u*1024u;
    __half* WoT    = wt_p + 5u*1024u*1024u;

    float* out  = (float*)d_out;
    float* attn = out + (size_t)NB * NL * ND;

    const int SM_BIG = NSTG * 2 * 128 * BP_BIG;          // 110592
    const int SM_CTX = NSTG * 15360 + 4096;              // 50176
    cudaFuncSetAttribute(mma_proj,  cudaFuncAttributeMaxDynamicSharedMemorySize, SM_BIG);
    cudaFuncSetAttribute(mma_out,   cudaFuncAttributeMaxDynamicSharedMemorySize, SM_BIG);
    cudaFuncSetAttribute(mma_score, cudaFuncAttributeMaxDynamicSharedMemorySize, SM_BIG);
    cudaFuncSetAttribute(mma_ctx,   cudaFuncAttributeMaxDynamicSharedMemorySize, SM_CTX);

    ProArgs pr;
    pr.q = (const float4*)query; pr.k = (const float4*)key; pr.v = (const float4*)value;
    pr.qh = (__half2*)qh_p; pr.kh = (__half2*)kh_p; pr.vh = (__half2*)vh_p;
    pr.wsrc[0] = Wpq; pr.wdst[0] = WqcatT + 0u*1024u*1024u;
    pr.wsrc[1] = Whq; pr.wdst[1] = WqcatT + 1u*1024u*1024u;
    pr.wsrc[2] = Wvq; pr.wdst[2] = WqcatT + 2u*1024u*1024u;
    pr.wsrc[3] = Wk;  pr.wdst[3] = WkT;
    pr.wsrc[4] = Wv;  pr.wdst[4] = WvT;
    pr.wsrc[5] = Wo;  pr.wdst[5] = WoT;
    pr.pc = pc; pr.bon = bon; pr.Wc = Wc; pr.bcW = bc; pr.Wb = Wb; pr.bbW = bb;
    pr.kcat = kcat_p;
    pr.bpq = bpq; pr.bhq = bhq; pr.bvq = bvq; pr.bcat = bcat_p;
    prologue<<<22540, 256>>>(pr);

    ProjArgs pa;
    pa.Aq = qh_p; pa.Ak = kh_p; pa.Av = vh_p;
    pa.Wq = WqcatT; pa.Wk = WkT; pa.Wv = WvT;
    pa.bq = bcat_p; pa.bk = bk; pa.bv = bv;
    pa.Cq = qcat_p; pa.Ck = kcat_p; pa.Cv = vt_p;
    mma_proj<<<dim3(40, 32), 256, SM_BIG>>>(pa);

    mma_score<<<dim3(8, 8, NBH), 256, SM_BIG>>>(qcat_p, kcat_p, pp_p, pmax_p, psum_p);
    mma_ctx<<<dim3(8, NBH), 256, SM_CTX>>>(pp_p, vt_p, pmax_p, psum_p, attn, ctx_p);
    mma_out<<<dim3(8, 32), 256, SM_BIG>>>(ctx_p, WoT, bo, out);
}